// round 2
// baseline (speedup 1.0000x reference)
#include <cuda_runtime.h>
#include <cuda_bf16.h>

// Problem constants (fixed by the reference)
#define NN 4096
#define KK 32
#define DD 256
#define HH 128
#define GG 384   // 3*H

typedef unsigned long long ull;

// ---------------- device scratch (no allocations allowed) ----------------
static __device__ float4 g_wih0p[64 * GG];   // W_ih0 packed [k4][g], k4 in 0..63
static __device__ float4 g_whh0p[32 * GG];   // W_hh0 packed
static __device__ float4 g_wih1p[32 * GG];   // W_ih1 packed
static __device__ float4 g_whh1p[32 * GG];   // W_hh1 packed
static __device__ float  g_xw0[NN * GG];     // x @ W_ih0^T + b_ih0   (6.3 MB)
static __device__ int    g_sorted[NN];
static __device__ int    g_off[KK + 1];
static __device__ int    g_len[KK];
static __device__ float  g_emb[KK * HH];
static __device__ float  g_wn[GG];
static __device__ float  g_scores[NN];
static __device__ float  g_clusum[KK];

// ---------------- f32x2 packed-FMA helpers ----------------
static __device__ __forceinline__ ull ffma2(ull a, ull b, ull c) {
    ull d;
    asm("fma.rn.f32x2 %0, %1, %2, %3;" : "=l"(d) : "l"(a), "l"(b), "l"(c));
    return d;
}
static __device__ __forceinline__ float f2sum(ull v) {
    float a, b;
    asm("mov.b64 {%0, %1}, %2;" : "=f"(a), "=f"(b) : "l"(v));
    return a + b;
}
static __device__ __forceinline__ float sigmoidf_(float x) {
    return 1.0f / (1.0f + expf(-x));
}

// ---------------- kernel: cluster ordering (stable) ----------------
__global__ void k_setup(const int* __restrict__ labels) {
    __shared__ int ls[NN];
    for (int i = threadIdx.x; i < NN; i += blockDim.x) ls[i] = labels[i];
    __syncthreads();
    if (threadIdx.x < 32) {
        int k = threadIdx.x;
        const int4* l4 = reinterpret_cast<const int4*>(ls);
        int cnt = 0;
        for (int ii = 0; ii < NN / 4; ++ii) {
            int4 v = l4[ii];
            cnt += (v.x == k) + (v.y == k) + (v.z == k) + (v.w == k);
        }
        g_len[k] = cnt;
        // warp exclusive prefix
        int v = cnt;
        #pragma unroll
        for (int d = 1; d < 32; d <<= 1) {
            int y = __shfl_up_sync(0xffffffffu, v, d);
            if (k >= d) v += y;
        }
        int off = v - cnt;
        g_off[k] = off;
        if (k == 31) g_off[32] = off + cnt;
        // stable scatter
        int c = off;
        for (int ii = 0; ii < NN / 4; ++ii) {
            int4 q = l4[ii];
            if (q.x == k) g_sorted[c++] = 4 * ii;
            if (q.y == k) g_sorted[c++] = 4 * ii + 1;
            if (q.z == k) g_sorted[c++] = 4 * ii + 2;
            if (q.w == k) g_sorted[c++] = 4 * ii + 3;
        }
    }
}

// ---------------- kernel: pack weights [g][k] -> [k4][g] float4 ----------------
__global__ void k_pack(const float* __restrict__ wih0, const float* __restrict__ whh0,
                       const float* __restrict__ wih1, const float* __restrict__ whh1) {
    int b = blockIdx.x;
    int g = threadIdx.x;
    const float* src;
    float4* dst;
    int k4, Kdim;
    if (b < 64)       { src = wih0; dst = g_wih0p; k4 = b;       Kdim = DD; }
    else if (b < 96)  { src = whh0; dst = g_whh0p; k4 = b - 64;  Kdim = HH; }
    else if (b < 128) { src = wih1; dst = g_wih1p; k4 = b - 96;  Kdim = HH; }
    else              { src = whh1; dst = g_whh1p; k4 = b - 128; Kdim = HH; }
    const float* row = src + (size_t)g * Kdim + k4 * 4;
    dst[k4 * GG + g] = make_float4(row[0], row[1], row[2], row[3]);
}

// ---------------- kernel: xw0 = x @ W_ih0^T + b_ih0 ----------------
__global__ void __launch_bounds__(384) k_xw0(const float* __restrict__ x,
                                             const float* __restrict__ b_ih0) {
    __shared__ __align__(16) float xs[16 * DD];   // 16 KB
    int r0 = blockIdx.x * 16;
    {
        const float4* xsrc = reinterpret_cast<const float4*>(x + (size_t)r0 * DD);
        float4* xd = reinterpret_cast<float4*>(xs);
        for (int i = threadIdx.x; i < 16 * DD / 4; i += 384) xd[i] = xsrc[i];
    }
    __syncthreads();
    int g = threadIdx.x;
    ull acc[16];
    #pragma unroll
    for (int s = 0; s < 16; ++s) acc[s] = 0ull;
    const ulonglong2* W = reinterpret_cast<const ulonglong2*>(g_wih0p) + g;
    #pragma unroll 8
    for (int k4 = 0; k4 < 64; ++k4) {
        ulonglong2 w = W[k4 * GG];
        #pragma unroll
        for (int s = 0; s < 16; ++s) {
            ulonglong2 xv = *reinterpret_cast<const ulonglong2*>(&xs[s * DD + k4 * 4]);
            acc[s] = ffma2(w.x, xv.x, acc[s]);
            acc[s] = ffma2(w.y, xv.y, acc[s]);
        }
    }
    float bi = b_ih0[g];
    #pragma unroll
    for (int s = 0; s < 16; ++s)
        g_xw0[(size_t)(r0 + s) * GG + g] = f2sum(acc[s]) + bi;
}

// ---------------- kernel: the GRU recurrence (2 clusters per block) ----------------
__global__ void __launch_bounds__(384, 1) k_rec(const float* __restrict__ b_ih0,
                                                const float* __restrict__ b_hh0,
                                                const float* __restrict__ b_ih1,
                                                const float* __restrict__ b_hh1) {
    __shared__ __align__(16) float h1s[2][HH];
    __shared__ __align__(16) float h2s[2][HH];
    __shared__ float hw0s[2][GG];
    __shared__ float hw1s[2][GG];
    __shared__ float xw1s[2][GG];

    int g  = threadIdx.x;
    int c0 = blockIdx.x;
    int c1 = blockIdx.x + 16;

    int len0 = g_len[c0], len1 = g_len[c1];
    int off0 = g_off[c0], off1 = g_off[c1];
    int le0 = max(len0, 1), le1 = max(len1, 1);
    int tmax = max(le0, le1);

    if (g < HH) { h1s[0][g] = 0.f; h1s[1][g] = 0.f; h2s[0][g] = 0.f; h2s[1][g] = 0.f; }
    float bh0 = b_hh0[g];
    float bi1 = b_ih1[g];
    float bh1 = b_hh1[g];
    __syncthreads();

    const ulonglong2* Whh0 = reinterpret_cast<const ulonglong2*>(g_whh0p) + g;
    const ulonglong2* Wih1 = reinterpret_cast<const ulonglong2*>(g_wih1p) + g;
    const ulonglong2* Whh1 = reinterpret_cast<const ulonglong2*>(g_whh1p) + g;

    for (int t = 0; t < tmax; ++t) {
        // ---- P1: hw0 = W_hh0 @ h1 (old), hw1 = W_hh1 @ h2 (old), both clusters
        ull a00 = 0ull, a01 = 0ull, a10 = 0ull, a11 = 0ull;
        #pragma unroll
        for (int k4 = 0; k4 < 32; ++k4) {
            ulonglong2 w0 = Whh0[k4 * GG];
            ulonglong2 w1 = Whh1[k4 * GG];
            ulonglong2 hA0 = *reinterpret_cast<const ulonglong2*>(&h1s[0][k4 * 4]);
            ulonglong2 hA1 = *reinterpret_cast<const ulonglong2*>(&h1s[1][k4 * 4]);
            ulonglong2 hB0 = *reinterpret_cast<const ulonglong2*>(&h2s[0][k4 * 4]);
            ulonglong2 hB1 = *reinterpret_cast<const ulonglong2*>(&h2s[1][k4 * 4]);
            a00 = ffma2(w0.x, hA0.x, a00); a00 = ffma2(w0.y, hA0.y, a00);
            a01 = ffma2(w0.x, hA1.x, a01); a01 = ffma2(w0.y, hA1.y, a01);
            a10 = ffma2(w1.x, hB0.x, a10); a10 = ffma2(w1.y, hB0.y, a10);
            a11 = ffma2(w1.x, hB1.x, a11); a11 = ffma2(w1.y, hB1.y, a11);
        }
        hw0s[0][g] = f2sum(a00) + bh0;
        hw0s[1][g] = f2sum(a01) + bh0;
        hw1s[0][g] = f2sum(a10) + bh1;
        hw1s[1][g] = f2sum(a11) + bh1;
        __syncthreads();

        // ---- P2: layer-0 gate update -> h1 (new)
        if (g < 2 * HH) {
            int c = g >> 7, j = g & (HH - 1);
            int len = c ? len1 : len0;
            int le  = c ? le1  : le0;
            int off = c ? off1 : off0;
            if (t < le) {
                float xr, xz, xn;
                if (t < len) {
                    int idx = g_sorted[off + t];
                    const float* xwp = g_xw0 + (size_t)idx * GG;
                    xr = xwp[j]; xz = xwp[HH + j]; xn = xwp[2 * HH + j];
                } else {  // empty cluster: one step with x = 0
                    xr = b_ih0[j]; xz = b_ih0[HH + j]; xn = b_ih0[2 * HH + j];
                }
                float r = sigmoidf_(xr + hw0s[c][j]);
                float z = sigmoidf_(xz + hw0s[c][HH + j]);
                float n = tanhf(xn + r * hw0s[c][2 * HH + j]);
                h1s[c][j] = (1.0f - z) * n + z * h1s[c][j];
            }
        }
        __syncthreads();

        // ---- P3: xw1 = W_ih1 @ h1 (new), both clusters
        ull b0 = 0ull, b1 = 0ull;
        #pragma unroll
        for (int k4 = 0; k4 < 32; ++k4) {
            ulonglong2 w = Wih1[k4 * GG];
            ulonglong2 p0 = *reinterpret_cast<const ulonglong2*>(&h1s[0][k4 * 4]);
            ulonglong2 p1 = *reinterpret_cast<const ulonglong2*>(&h1s[1][k4 * 4]);
            b0 = ffma2(w.x, p0.x, b0); b0 = ffma2(w.y, p0.y, b0);
            b1 = ffma2(w.x, p1.x, b1); b1 = ffma2(w.y, p1.y, b1);
        }
        xw1s[0][g] = f2sum(b0) + bi1;
        xw1s[1][g] = f2sum(b1) + bi1;
        __syncthreads();

        // ---- P4: layer-1 gate update -> h2 (new)
        if (g < 2 * HH) {
            int c = g >> 7, j = g & (HH - 1);
            int le = c ? le1 : le0;
            if (t < le) {
                float r = sigmoidf_(xw1s[c][j] + hw1s[c][j]);
                float z = sigmoidf_(xw1s[c][HH + j] + hw1s[c][HH + j]);
                float n = tanhf(xw1s[c][2 * HH + j] + r * hw1s[c][2 * HH + j]);
                h2s[c][j] = (1.0f - z) * n + z * h2s[c][j];
            }
        }
        __syncthreads();
    }

    if (g < 2 * HH) {
        int c = g >> 7, j = g & (HH - 1);
        g_emb[(c ? c1 : c0) * HH + j] = h2s[c][j];
    }
}

// ---------------- kernel: weight-normed linear weights ----------------
__global__ void k_wn(const float* __restrict__ lin_v, const float* __restrict__ lin_g) {
    __shared__ float red[512];
    int g = threadIdx.x;  // 384 threads
    float v = lin_v[g];
    red[g] = v * v;
    if (g < 128) red[384 + g] = 0.f;
    __syncthreads();
    #pragma unroll
    for (int s = 256; s >= 1; s >>= 1) {
        if (g < s) red[g] += red[g + s];
        __syncthreads();
    }
    float invn = 1.0f / sqrtf(red[0]);
    g_wn[g] = lin_g[0] * v * invn;
}

// ---------------- kernel: per-sentence tanh scores ----------------
__global__ void __launch_bounds__(128) k_score(const float* __restrict__ x,
                                               const int* __restrict__ labels,
                                               const float* __restrict__ lin_b) {
    __shared__ __align__(16) float wns[GG];
    __shared__ __align__(16) float embs[KK][132];  // padded to dodge bank conflicts
    for (int i = threadIdx.x; i < GG; i += 128) wns[i] = g_wn[i];
    for (int i = threadIdx.x; i < KK * HH; i += 128) embs[i >> 7][i & 127] = g_emb[i];
    __syncthreads();
    int i = blockIdx.x * 128 + threadIdx.x;
    int lab = labels[i];
    const float4* xr = reinterpret_cast<const float4*>(x) + (size_t)i * (DD / 4);
    float acc = 0.f;
    #pragma unroll 8
    for (int k4 = 0; k4 < DD / 4; ++k4) {
        float4 xv = xr[k4];
        float4 wv = *reinterpret_cast<const float4*>(&wns[k4 * 4]);
        acc = fmaf(xv.x, wv.x, acc); acc = fmaf(xv.y, wv.y, acc);
        acc = fmaf(xv.z, wv.z, acc); acc = fmaf(xv.w, wv.w, acc);
    }
    #pragma unroll 8
    for (int k4 = 0; k4 < HH / 4; ++k4) {
        float4 ev = *reinterpret_cast<const float4*>(&embs[lab][k4 * 4]);
        float4 wv = *reinterpret_cast<const float4*>(&wns[DD + k4 * 4]);
        acc = fmaf(ev.x, wv.x, acc); acc = fmaf(ev.y, wv.y, acc);
        acc = fmaf(ev.z, wv.z, acc); acc = fmaf(ev.w, wv.w, acc);
    }
    g_scores[i] = tanhf(acc + lin_b[0]);
}

// ---------------- kernel: deterministic per-cluster score sums ----------------
__global__ void __launch_bounds__(128) k_clusum() {
    __shared__ float red[128];
    int k = blockIdx.x;
    int len = g_len[k], off = g_off[k];
    float s = 0.f;
    for (int t = threadIdx.x; t < len; t += 128) s += g_scores[g_sorted[off + t]];
    red[threadIdx.x] = s;
    __syncthreads();
    #pragma unroll
    for (int d = 64; d >= 1; d >>= 1) {
        if (threadIdx.x < d) red[threadIdx.x] += red[threadIdx.x + d];
        __syncthreads();
    }
    if (threadIdx.x == 0) g_clusum[k] = red[0];
}

// ---------------- kernel: final blend ----------------
__global__ void k_final(const int* __restrict__ labels, float* __restrict__ out) {
    int i = blockIdx.x * blockDim.x + threadIdx.x;
    if (i >= NN) return;
    const float INV = 0.0625f;  // 1 / 4096^(1/3)
    float sal = g_scores[i] / g_clusum[labels[i]];
    float pos = fmaxf(0.5f, expf(-((float)(i + 1)) * INV));
    out[i] = 0.5f * sal + 0.5f * pos;
}

// ---------------- launch ----------------
extern "C" void kernel_launch(void* const* d_in, const int* in_sizes, int n_in,
                              void* d_out, int out_size) {
    const float* x      = (const float*)d_in[0];
    const int*   labels = (const int*)d_in[1];
    const float* W_ih0  = (const float*)d_in[2];
    const float* W_hh0  = (const float*)d_in[3];
    const float* b_ih0  = (const float*)d_in[4];
    const float* b_hh0  = (const float*)d_in[5];
    const float* W_ih1  = (const float*)d_in[6];
    const float* W_hh1  = (const float*)d_in[7];
    const float* b_ih1  = (const float*)d_in[8];
    const float* b_hh1  = (const float*)d_in[9];
    const float* lin_v  = (const float*)d_in[10];
    const float* lin_g  = (const float*)d_in[11];
    const float* lin_b  = (const float*)d_in[12];
    float* out = (float*)d_out;

    k_setup<<<1, 256>>>(labels);
    k_pack<<<160, 384>>>(W_ih0, W_hh0, W_ih1, W_hh1);
    k_xw0<<<NN / 16, 384>>>(x, b_ih0);
    k_rec<<<16, 384>>>(b_ih0, b_hh0, b_ih1, b_hh1);
    k_wn<<<1, 384>>>(lin_v, lin_g);
    k_score<<<NN / 128, 128>>>(x, labels, lin_b);
    k_clusum<<<KK, 128>>>();
    k_final<<<16, 256>>>(labels, out);
}

// round 3
// speedup vs baseline: 2.4504x; 2.4504x over previous
#include <cuda_runtime.h>
#include <cuda_bf16.h>

// Problem constants (fixed by the reference)
#define NN 4096
#define KK 32
#define DD 256
#define HH 128
#define GG 384   // 3*H

typedef unsigned long long ull;

// ---------------- device scratch (no allocations allowed) ----------------
static __device__ float4 g_wih0p[64 * GG];   // W_ih0 packed [k4][g] for k_xw0
static __device__ float  g_xw0[NN * GG];     // x @ W_ih0^T + b_ih0   (6.3 MB)
static __device__ int    g_sorted[NN];
static __device__ int    g_off[KK + 1];
static __device__ int    g_len[KK];
static __device__ float  g_emb[KK * HH];
static __device__ float  g_wn[GG];
static __device__ float  g_scores[NN];
static __device__ float  g_clusum[KK];

// ---------------- f32x2 packed-FMA helpers ----------------
static __device__ __forceinline__ ull ffma2(ull a, ull b, ull c) {
    ull d;
    asm("fma.rn.f32x2 %0, %1, %2, %3;" : "=l"(d) : "l"(a), "l"(b), "l"(c));
    return d;
}
static __device__ __forceinline__ float f2sum(ull v) {
    float a, b;
    asm("mov.b64 {%0, %1}, %2;" : "=f"(a), "=f"(b) : "l"(v));
    return a + b;
}
static __device__ __forceinline__ float sigmoidf_(float x) {
    return 1.0f / (1.0f + expf(-x));
}
static __device__ __forceinline__ unsigned mapa32(unsigned a, int r) {
    unsigned d;
    asm("mapa.shared::cluster.u32 %0, %1, %2;" : "=r"(d) : "r"(a), "r"(r));
    return d;
}
static __device__ __forceinline__ void stremote(unsigned a, float v) {
    asm volatile("st.shared::cluster.f32 [%0], %1;" :: "r"(a), "f"(v) : "memory");
}
#define CLUSTER_ARRIVE() asm volatile("barrier.cluster.arrive.aligned;" ::: "memory")
#define CLUSTER_WAIT()   asm volatile("barrier.cluster.wait.aligned;"   ::: "memory")

// ---------------- kernel: cluster ordering (stable, parallel) ----------------
__global__ void k_setup(const int* __restrict__ labels) {
    __shared__ int ls[NN];
    __shared__ int cnt[8][KK];
    __shared__ int soff[8][KK];
    int t = threadIdx.x;                 // 256 threads
    for (int i = t; i < NN; i += 256) ls[i] = labels[i];
    __syncthreads();
    int w = t >> 5, k = t & 31;
    {
        int c = 0;
        const int4* p = (const int4*)(ls + w * 512);
        for (int ii = 0; ii < 128; ++ii) {
            int4 v = p[ii];
            c += (v.x == k) + (v.y == k) + (v.z == k) + (v.w == k);
        }
        cnt[w][k] = c;
    }
    __syncthreads();
    if (w == 0) {
        int tot = 0;
        #pragma unroll
        for (int s = 0; s < 8; ++s) tot += cnt[s][k];
        g_len[k] = tot;
        int v = tot;
        #pragma unroll
        for (int d = 1; d < 32; d <<= 1) {
            int y = __shfl_up_sync(0xffffffffu, v, d);
            if (k >= d) v += y;
        }
        int off = v - tot;
        g_off[k] = off;
        if (k == 31) g_off[32] = off + tot;
        int run = off;
        #pragma unroll
        for (int s = 0; s < 8; ++s) { soff[s][k] = run; run += cnt[s][k]; }
    }
    __syncthreads();
    {
        int c = soff[w][k];
        const int4* p = (const int4*)(ls + w * 512);
        for (int ii = 0; ii < 128; ++ii) {
            int4 v = p[ii];
            int b = w * 512 + ii * 4;
            if (v.x == k) g_sorted[c++] = b;
            if (v.y == k) g_sorted[c++] = b + 1;
            if (v.z == k) g_sorted[c++] = b + 2;
            if (v.w == k) g_sorted[c++] = b + 3;
        }
    }
}

// ---------------- kernel: pack W_ih0 [g][k] -> [k4][g] float4 ----------------
__global__ void k_pack(const float* __restrict__ wih0) {
    int k4 = blockIdx.x;        // 0..63
    int g  = threadIdx.x;       // 0..383
    const float* row = wih0 + (size_t)g * DD + k4 * 4;
    g_wih0p[k4 * GG + g] = make_float4(row[0], row[1], row[2], row[3]);
}

// ---------------- kernel: xw0 = x @ W_ih0^T + b_ih0 ----------------
__global__ void __launch_bounds__(384) k_xw0(const float* __restrict__ x,
                                             const float* __restrict__ b_ih0) {
    __shared__ __align__(16) float xs[16 * DD];   // 16 KB
    int r0 = blockIdx.x * 16;
    {
        const float4* xsrc = reinterpret_cast<const float4*>(x + (size_t)r0 * DD);
        float4* xd = reinterpret_cast<float4*>(xs);
        for (int i = threadIdx.x; i < 16 * DD / 4; i += 384) xd[i] = xsrc[i];
    }
    __syncthreads();
    int g = threadIdx.x;
    ull acc[16];
    #pragma unroll
    for (int s = 0; s < 16; ++s) acc[s] = 0ull;
    const ulonglong2* W = reinterpret_cast<const ulonglong2*>(g_wih0p) + g;
    #pragma unroll 8
    for (int k4 = 0; k4 < 64; ++k4) {
        ulonglong2 w = W[k4 * GG];
        #pragma unroll
        for (int s = 0; s < 16; ++s) {
            ulonglong2 xv = *reinterpret_cast<const ulonglong2*>(&xs[s * DD + k4 * 4]);
            acc[s] = ffma2(w.x, xv.x, acc[s]);
            acc[s] = ffma2(w.y, xv.y, acc[s]);
        }
    }
    float bi = b_ih0[g];
    #pragma unroll
    for (int s = 0; s < 16; ++s)
        g_xw0[(size_t)(r0 + s) * GG + g] = f2sum(acc[s]) + bi;
}

// ---------------- kernel: GRU recurrence ----------------
// 32 CGAs (one GRU cluster each) x 4 CTAs. Each CTA holds 96 of the 384 gate
// rows of Whh0/Whh1/Wih1 in REGISTERS (hidden slice j in [32*rank, 32*rank+32)).
// Layer 1 lags layer 0 by one step, so all three matvecs read already-synced
// state -> ONE cluster barrier per step. h double-buffered by step parity.
__global__ void __cluster_dims__(4, 1, 1) __launch_bounds__(384, 1)
k_rec(const float* __restrict__ Whh0, const float* __restrict__ Wih1,
      const float* __restrict__ Whh1,
      const float* __restrict__ b_ih0, const float* __restrict__ b_hh0,
      const float* __restrict__ b_ih1, const float* __restrict__ b_hh1) {
    __shared__ __align__(16) float h1s[2][HH];
    __shared__ __align__(16) float h2s[2][HH];
    __shared__ float hw0s[96], hw1s[96], xw1s[96];
    __shared__ __align__(16) float stage[48 * 132];

    const int t = threadIdx.x;
    const int c = blockIdx.x >> 2;
    int rank_;
    asm("mov.u32 %0, %%cluster_ctarank;" : "=r"(rank_));
    const int rank = rank_;

    const int rr = t >> 2;        // 0..95: output row within this CTA's slice
    const int q  = t & 3;         // k-quarter (32 values each)
    const int mrow = (rr >> 5) * HH + 32 * rank + (rr & 31);  // global gate row

    float bh0 = b_hh0[mrow], bh1 = b_hh1[mrow], bi1 = b_ih1[mrow];

    if (t < HH) { h1s[0][t] = 0.f; h1s[1][t] = 0.f; h2s[0][t] = 0.f; h2s[1][t] = 0.f; }

    // ---- load per-thread weight slices into registers (coalesced via smem stage)
    ulonglong2 wA[8], wB[8], wC[8];
#define LOADW(SRC, DST)                                                           \
    for (int hrow = 0; hrow < 2; ++hrow) {                                        \
        _Pragma("unroll")                                                         \
        for (int qq = 0; qq < 4; ++qq) {                                          \
            int f4i = t * 4 + qq;                                                 \
            int rline = f4i >> 5, c4 = f4i & 31;                                  \
            int rr2 = hrow * 48 + rline;                                          \
            int m2 = (rr2 >> 5) * HH + 32 * rank + (rr2 & 31);                    \
            *(float4*)&stage[rline * 132 + c4 * 4] =                              \
                *(const float4*)(SRC + (size_t)m2 * HH + c4 * 4);                 \
        }                                                                         \
        __syncthreads();                                                          \
        if (rr >= hrow * 48 && rr < hrow * 48 + 48) {                             \
            int rline = rr - hrow * 48;                                           \
            _Pragma("unroll")                                                     \
            for (int i = 0; i < 8; ++i)                                           \
                DST[i] = *(const ulonglong2*)&stage[rline * 132 + q * 32 + i * 4];\
        }                                                                         \
        __syncthreads();                                                          \
    }
    LOADW(Whh0, wA)
    LOADW(Whh1, wB)
    LOADW(Wih1, wC)
#undef LOADW

    // ---- gate-thread input prefetch state
    const int len = g_len[c];
    const int off = g_off[c];
    const int len_e = max(len, 1);
    float xr_c = 0.f, xz_c = 0.f, xn_c = 0.f;
    int idxA = 0;
    if (t < 32) {
        int j = 32 * rank + t;
        if (len > 0) {
            int i0 = g_sorted[off];
            const float* p = g_xw0 + (size_t)i0 * GG;
            xr_c = p[j]; xz_c = p[HH + j]; xn_c = p[2 * HH + j];
        } else {  // empty cluster: single step with x = 0 (xw = b_ih0)
            xr_c = b_ih0[j]; xz_c = b_ih0[HH + j]; xn_c = b_ih0[2 * HH + j];
        }
        if (len > 1) idxA = g_sorted[off + 1];
    }

    // ---- peer DSMEM addresses for the three other CTAs
    unsigned h1b = (unsigned)__cvta_generic_to_shared(&h1s[0][0]);
    unsigned h2b = (unsigned)__cvta_generic_to_shared(&h2s[0][0]);
    unsigned ph1[3], ph2[3];
    {
        int pi = 0;
        #pragma unroll
        for (int rp = 0; rp < 4; ++rp)
            if (rp != rank) { ph1[pi] = mapa32(h1b, rp); ph2[pi] = mapa32(h2b, rp); ++pi; }
    }

    CLUSTER_ARRIVE();
    CLUSTER_WAIT();

    // Invariant at iteration `it`: h1s[p] = h1 after `it` layer-0 steps,
    // h2s[p] = h2 after (it-1) layer-1 steps, p = it&1.
    for (int it = 0; it <= len_e; ++it) {
        const int p = it & 1;
        // ---- three matvecs from register weights + broadcast smem h
        ull a0x = 0, a0y = 0, a1x = 0, a1y = 0, a2x = 0, a2y = 0;
        const ulonglong2* h1p = (const ulonglong2*)&h1s[p][0] + q * 8;
        const ulonglong2* h2p = (const ulonglong2*)&h2s[p][0] + q * 8;
        #pragma unroll
        for (int i = 0; i < 8; ++i) {
            ulonglong2 hv1 = h1p[i];
            a0x = ffma2(wA[i].x, hv1.x, a0x); a0y = ffma2(wA[i].y, hv1.y, a0y);
            a2x = ffma2(wC[i].x, hv1.x, a2x); a2y = ffma2(wC[i].y, hv1.y, a2y);
            ulonglong2 hv2 = h2p[i];
            a1x = ffma2(wB[i].x, hv2.x, a1x); a1y = ffma2(wB[i].y, hv2.y, a1y);
        }
        float s0 = f2sum(a0x) + f2sum(a0y);
        float s1 = f2sum(a1x) + f2sum(a1y);
        float s2 = f2sum(a2x) + f2sum(a2y);
        s0 += __shfl_xor_sync(0xffffffffu, s0, 1); s0 += __shfl_xor_sync(0xffffffffu, s0, 2);
        s1 += __shfl_xor_sync(0xffffffffu, s1, 1); s1 += __shfl_xor_sync(0xffffffffu, s1, 2);
        s2 += __shfl_xor_sync(0xffffffffu, s2, 1); s2 += __shfl_xor_sync(0xffffffffu, s2, 2);
        if (q == 0)      hw0s[rr] = s0 + bh0;   // Whh0 @ h1
        else if (q == 1) hw1s[rr] = s1 + bh1;   // Whh1 @ h2
        else if (q == 2) xw1s[rr] = s2 + bi1;   // Wih1 @ h1
        __syncthreads();

        // ---- layer-0 gate update (threads 0..31): h1[it] from h1[it-1]
        if (t < 32 && it < len_e) {
            int j = 32 * rank + t;
            float r = sigmoidf_(xr_c + hw0s[t]);
            float z = sigmoidf_(xz_c + hw0s[32 + t]);
            float n = tanhf(xn_c + r * hw0s[64 + t]);
            float hn = (1.0f - z) * n + z * h1s[p][j];
            h1s[p ^ 1][j] = hn;
            unsigned o = (unsigned)(((p ^ 1) * HH + j) * 4);
            stremote(ph1[0] + o, hn); stremote(ph1[1] + o, hn); stremote(ph1[2] + o, hn);
        }
        // ---- layer-1 gate update, lagged (threads 32..63): h2[it-1]
        else if (t >= 32 && t < 64 && it >= 1) {
            int j2 = t - 32;
            int j = 32 * rank + j2;
            float r = sigmoidf_(xw1s[j2] + hw1s[j2]);
            float z = sigmoidf_(xw1s[32 + j2] + hw1s[32 + j2]);
            float n = tanhf(xw1s[64 + j2] + r * hw1s[64 + j2]);
            float hn = (1.0f - z) * n + z * h2s[p][j];
            h2s[p ^ 1][j] = hn;
            unsigned o = (unsigned)(((p ^ 1) * HH + j) * 4);
            stremote(ph2[0] + o, hn); stremote(ph2[1] + o, hn); stremote(ph2[2] + o, hn);
        }

        CLUSTER_ARRIVE();
        // ---- prefetch next sentence's xw0 while the barrier settles
        if (t < 32) {
            if (it + 1 < len) {
                const float* pp = g_xw0 + (size_t)idxA * GG;
                int j = 32 * rank + t;
                xr_c = pp[j]; xz_c = pp[HH + j]; xn_c = pp[2 * HH + j];
            }
            if (it + 2 < len) idxA = g_sorted[off + it + 2];
        }
        CLUSTER_WAIT();
    }

    if (rank == 0 && t < HH) g_emb[c * HH + t] = h2s[(len_e + 1) & 1][t];
}

// ---------------- kernel: weight-normed linear weights ----------------
__global__ void k_wn(const float* __restrict__ lin_v, const float* __restrict__ lin_g) {
    __shared__ float red[512];
    int g = threadIdx.x;  // 384 threads
    float v = lin_v[g];
    red[g] = v * v;
    if (g < 128) red[384 + g] = 0.f;
    __syncthreads();
    #pragma unroll
    for (int s = 256; s >= 1; s >>= 1) {
        if (g < s) red[g] += red[g + s];
        __syncthreads();
    }
    float invn = 1.0f / sqrtf(red[0]);
    g_wn[g] = lin_g[0] * v * invn;
}

// ---------------- kernel: per-sentence tanh scores ----------------
__global__ void __launch_bounds__(128) k_score(const float* __restrict__ x,
                                               const int* __restrict__ labels,
                                               const float* __restrict__ lin_b) {
    __shared__ __align__(16) float wns[GG];
    __shared__ __align__(16) float embs[KK][132];  // padded
    for (int i = threadIdx.x; i < GG; i += 128) wns[i] = g_wn[i];
    for (int i = threadIdx.x; i < KK * HH; i += 128) embs[i >> 7][i & 127] = g_emb[i];
    __syncthreads();
    int i = blockIdx.x * 128 + threadIdx.x;
    int lab = labels[i];
    const float4* xr = reinterpret_cast<const float4*>(x) + (size_t)i * (DD / 4);
    float acc = 0.f;
    #pragma unroll 8
    for (int k4 = 0; k4 < DD / 4; ++k4) {
        float4 xv = xr[k4];
        float4 wv = *reinterpret_cast<const float4*>(&wns[k4 * 4]);
        acc = fmaf(xv.x, wv.x, acc); acc = fmaf(xv.y, wv.y, acc);
        acc = fmaf(xv.z, wv.z, acc); acc = fmaf(xv.w, wv.w, acc);
    }
    #pragma unroll 8
    for (int k4 = 0; k4 < HH / 4; ++k4) {
        float4 ev = *reinterpret_cast<const float4*>(&embs[lab][k4 * 4]);
        float4 wv = *reinterpret_cast<const float4*>(&wns[DD + k4 * 4]);
        acc = fmaf(ev.x, wv.x, acc); acc = fmaf(ev.y, wv.y, acc);
        acc = fmaf(ev.z, wv.z, acc); acc = fmaf(ev.w, wv.w, acc);
    }
    g_scores[i] = tanhf(acc + lin_b[0]);
}

// ---------------- kernel: deterministic per-cluster score sums ----------------
__global__ void __launch_bounds__(128) k_clusum() {
    __shared__ float red[128];
    int k = blockIdx.x;
    int len = g_len[k], off = g_off[k];
    float s = 0.f;
    for (int t = threadIdx.x; t < len; t += 128) s += g_scores[g_sorted[off + t]];
    red[threadIdx.x] = s;
    __syncthreads();
    #pragma unroll
    for (int d = 64; d >= 1; d >>= 1) {
        if (threadIdx.x < d) red[threadIdx.x] += red[threadIdx.x + d];
        __syncthreads();
    }
    if (threadIdx.x == 0) g_clusum[k] = red[0];
}

// ---------------- kernel: final blend ----------------
__global__ void k_final(const int* __restrict__ labels, float* __restrict__ out) {
    int i = blockIdx.x * blockDim.x + threadIdx.x;
    if (i >= NN) return;
    const float INV = 0.0625f;  // 1 / 4096^(1/3)
    float sal = g_scores[i] / g_clusum[labels[i]];
    float pos = fmaxf(0.5f, expf(-((float)(i + 1)) * INV));
    out[i] = 0.5f * sal + 0.5f * pos;
}

// ---------------- launch ----------------
extern "C" void kernel_launch(void* const* d_in, const int* in_sizes, int n_in,
                              void* d_out, int out_size) {
    const float* x      = (const float*)d_in[0];
    const int*   labels = (const int*)d_in[1];
    const float* W_ih0  = (const float*)d_in[2];
    const float* W_hh0  = (const float*)d_in[3];
    const float* b_ih0  = (const float*)d_in[4];
    const float* b_hh0  = (const float*)d_in[5];
    const float* W_ih1  = (const float*)d_in[6];
    const float* W_hh1  = (const float*)d_in[7];
    const float* b_ih1  = (const float*)d_in[8];
    const float* b_hh1  = (const float*)d_in[9];
    const float* lin_v  = (const float*)d_in[10];
    const float* lin_g  = (const float*)d_in[11];
    const float* lin_b  = (const float*)d_in[12];
    float* out = (float*)d_out;

    k_setup<<<1, 256>>>(labels);
    k_pack<<<64, 384>>>(W_ih0);
    k_xw0<<<NN / 16, 384>>>(x, b_ih0);
    k_rec<<<128, 384>>>(W_hh0, W_ih1, W_hh1, b_ih0, b_hh0, b_ih1, b_hh1);
    k_wn<<<1, 384>>>(lin_v, lin_g);
    k_score<<<NN / 128, 128>>>(x, labels, lin_b);
    k_clusum<<<KK, 128>>>();
    k_final<<<16, 256>>>(labels, out);
}